// round 16
// baseline (speedup 1.0000x reference)
#include <cuda_runtime.h>
#include <cuda_fp16.h>
#include <cstdint>

#define NB 12
#define DM 128
#define NH 2
#define HD 64

struct Consts {
    float ta[NH];
    float u[NH];
    float bo;
    float pad[3];
    float tb[NH][NB];
    float gam[NH][NB];
    float w[NH][NB];
    float del[NH][NB][NB];
};

__device__ __align__(16) Consts g_c;

__device__ __forceinline__ __half2 h2ex2(__half2 v) {
    uint32_t a = *reinterpret_cast<uint32_t*>(&v), b;
    asm("ex2.approx.f16x2 %0, %1;" : "=r"(b) : "r"(a));
    return *reinterpret_cast<__half2*>(&b);
}

// ---------------------------------------------------------------------------
// Setup: ONE node, TWO blocks (one per head). All constants for head h are
// dots over head h's 64 components only -> blocks write DISJOINT fields of
// g_c directly. No partials, no reduction node.
// Two-phase smem GEMM: stage Wq rows -> C[0..63][13]; restage Wk -> C[64..127].
// Static smem: 33,792 (W pad33) + 6,656 (E) + 6,656 (C) + 512 (vproj) = 47.6KB.
// ---------------------------------------------------------------------------
__global__ void __launch_bounds__(256) spec_setup(
        const float* __restrict__ we, const float* __restrict__ be,
        const float* __restrict__ bp,
        const float* __restrict__ Wq, const float* __restrict__ bq,
        const float* __restrict__ Wk, const float* __restrict__ bk,
        const float* __restrict__ Wv, const float* __restrict__ bv,
        const float* __restrict__ Wo, const float* __restrict__ bo) {
    __shared__ __align__(16) float4 sW4[64 * 33];
    __shared__ __align__(16) float4 sE4[13][32];
    __shared__ __align__(16) float  sC[128][13];
    __shared__ float sVP[DM];

    const int tid = threadIdx.x;
    const int h = blockIdx.x;          // 0..1
    const int ibase = h * HD;

    // ---- stage E = [we, be+bp[0..11]] ----
    for (int idx = tid; idx < 13 * 32; idx += 256) {
        int e = idx >> 5, c = idx & 31;
        float4 v;
        if (e == 0) {
            v = ((const float4*)we)[c];
        } else {
            float4 b4 = ((const float4*)be)[c];
            float4 p4 = ((const float4*)bp)[(e - 1) * 32 + c];
            v = make_float4(b4.x + p4.x, b4.y + p4.y, b4.z + p4.z, b4.w + p4.w);
        }
        sE4[e][c] = v;
    }

    // ---- vproj partials (scratch aliased into sC storage, used & freed
    //      before the GEMM writes sC) ----
    {
        float4* sVPw = (float4*)&sC[0][0];       // 8 warps x 32 lanes x f4 = 4KB
        int wid = tid >> 5, lane = tid & 31;
        float4 p = make_float4(0.f, 0.f, 0.f, 0.f);
        #pragma unroll
        for (int k = 0; k < 8; k++) {
            int i = ibase + wid * 8 + k;
            float wo = Wo[i];
            float4 v4 = ((const float4*)(Wv + i * DM))[lane];
            p.x = fmaf(wo, v4.x, p.x);
            p.y = fmaf(wo, v4.y, p.y);
            p.z = fmaf(wo, v4.z, p.z);
            p.w = fmaf(wo, v4.w, p.w);
        }
        sVPw[wid * 32 + lane] = p;
    }
    __syncthreads();
    if (tid < 32) {
        const float4* sVPw = (const float4*)&sC[0][0];
        float4 s = make_float4(0.f, 0.f, 0.f, 0.f);
        #pragma unroll
        for (int w = 0; w < 8; w++) {
            float4 p = sVPw[w * 32 + tid];
            s.x += p.x; s.y += p.y; s.z += p.z; s.w += p.w;
        }
        ((float4*)sVP)[tid] = s;
    }
    __syncthreads();   // sVP ready; sC scratch free

    // ---- phase A: Wq rows -> C[0..63][13]; phase B: Wk -> C[64..127][13] ----
    #pragma unroll
    for (int ph = 0; ph < 2; ph++) {
        const float* W  = (ph == 0) ? Wq : Wk;
        const float* bb = (ph == 0) ? bq : bk;
        for (int idx = tid; idx < 64 * 32; idx += 256) {
            int r = idx >> 5, c = idx & 31;
            sW4[r * 33 + c] = ((const float4*)(W + (ibase + r) * DM))[c];
        }
        __syncthreads();
        for (int idx = tid; idx < 64 * 13; idx += 256) {
            int r = idx & 63;
            int e = idx >> 6;
            float a0 = 0.f, a1 = 0.f, a2 = 0.f, a3 = 0.f;
            #pragma unroll
            for (int c = 0; c < 32; c += 4) {
                float4 w0 = sW4[r * 33 + c],     e0 = sE4[e][c];
                float4 w1 = sW4[r * 33 + c + 1], e1 = sE4[e][c + 1];
                float4 w2 = sW4[r * 33 + c + 2], e2 = sE4[e][c + 2];
                float4 w3 = sW4[r * 33 + c + 3], e3 = sE4[e][c + 3];
                a0 = fmaf(w0.x, e0.x, fmaf(w0.y, e0.y, fmaf(w0.z, e0.z, fmaf(w0.w, e0.w, a0))));
                a1 = fmaf(w1.x, e1.x, fmaf(w1.y, e1.y, fmaf(w1.z, e1.z, fmaf(w1.w, e1.w, a1))));
                a2 = fmaf(w2.x, e2.x, fmaf(w2.y, e2.y, fmaf(w2.z, e2.z, fmaf(w2.w, e2.w, a2))));
                a3 = fmaf(w3.x, e3.x, fmaf(w3.y, e3.y, fmaf(w3.z, e3.z, fmaf(w3.w, e3.w, a3))));
            }
            float acc = (a0 + a1) + (a2 + a3);
            if (e > 0) acc += bb[ibase + r];
            sC[ph * 64 + r][e] = acc;
        }
        __syncthreads();
    }

    // ---- phase 2: all 182 constants of head h (dots over 64 rows) ----
    const float cfac = 0.125f * 1.4426950408889634f;  // (1/sqrt(64))*log2(e)

    if (tid < 182) {
        int rr = tid;
        if (rr == 1 || (rr >= 26 && rr < 38)) {
            // dot-128 of vproj with an E vector (u and w[b])
            int e = (rr == 1) ? 0 : (rr - 26 + 1);
            const float4* A = (const float4*)sVP;
            float a0 = 0.f, a1 = 0.f, a2 = 0.f, a3 = 0.f;
            #pragma unroll
            for (int c = 0; c < 32; c += 4) {
                float4 v0 = A[c],     e0 = sE4[e][c];
                float4 v1 = A[c + 1], e1 = sE4[e][c + 1];
                float4 v2 = A[c + 2], e2 = sE4[e][c + 2];
                float4 v3 = A[c + 3], e3 = sE4[e][c + 3];
                a0 = fmaf(v0.x, e0.x, fmaf(v0.y, e0.y, fmaf(v0.z, e0.z, fmaf(v0.w, e0.w, a0))));
                a1 = fmaf(v1.x, e1.x, fmaf(v1.y, e1.y, fmaf(v1.z, e1.z, fmaf(v1.w, e1.w, a1))));
                a2 = fmaf(v2.x, e2.x, fmaf(v2.y, e2.y, fmaf(v2.z, e2.z, fmaf(v2.w, e2.w, a2))));
                a3 = fmaf(v3.x, e3.x, fmaf(v3.y, e3.y, fmaf(v3.z, e3.z, fmaf(v3.w, e3.w, a3))));
            }
            float acc = (a0 + a1) + (a2 + a3);
            if (rr == 1) {
                g_c.u[h] = acc;
            } else {
                float bw = 0.f;
                #pragma unroll 8
                for (int il = 0; il < HD; il++)
                    bw = fmaf(bv[ibase + il], Wo[ibase + il], bw);
                g_c.w[h][rr - 26] = acc + bw;
            }
        } else {
            // dot-64: q-row column vs k-row column of sC
            int colA, colB;
            float* dst;
            if (rr == 0)      { colA = 0; colB = 0; dst = &g_c.ta[h]; }
            else if (rr < 14) { colA = 0; colB = 1 + (rr - 2);  dst = &g_c.tb[h][rr - 2]; }
            else if (rr < 26) { colA = 1 + (rr - 14); colB = 0; dst = &g_c.gam[h][rr - 14]; }
            else {
                int idx = rr - 38, q = idx / NB, k = idx % NB;
                colA = 1 + q; colB = 1 + k; dst = &g_c.del[h][q][k];
            }
            const float* A = &sC[0][colA];
            const float* B = &sC[64][colB];
            float a0 = 0.f, a1 = 0.f;
            #pragma unroll 8
            for (int il = 0; il < HD; il += 2) {
                a0 = fmaf(A[il * 13],       B[il * 13],       a0);
                a1 = fmaf(A[(il + 1) * 13], B[(il + 1) * 13], a1);
            }
            *dst = (a0 + a1) * cfac;
        }
    }
    if (h == 0 && tid == 182) g_c.bo = bo[0];
}

// ---------------------------------------------------------------------------
// Main kernel: proven fp16x2 core with the single-struct prologue
// (round-9/10 configuration, main ~9.7us).
// ---------------------------------------------------------------------------
__global__ void __launch_bounds__(256, 4) spec_main(const float* __restrict__ x,
                                                    float* __restrict__ out, int N2) {
    __shared__ __half2 sDel[NH][NB][8];
    __shared__ __half2 sTb[NH][6], sW[NH][6];
    __shared__ __half2 sGam[NH][NB];
    __shared__ __half2 sTa[NH], sU[NH];
    __shared__ float sBo;

    {
        int td = threadIdx.x;
        for (int i = td; i < NH * NB * 6; i += 256) {
            int hh = i / (NB * 6);
            int r = i % (NB * 6);
            int q = r / 6, j = r % 6;
            sDel[hh][q][j] = __floats2half2_rn(g_c.del[hh][q][2 * j],
                                               g_c.del[hh][q][2 * j + 1]);
        }
        if (td < NH * 6) {
            int hh = td / 6, j = td % 6;
            sTb[hh][j] = __floats2half2_rn(g_c.tb[hh][2 * j], g_c.tb[hh][2 * j + 1]);
            sW[hh][j]  = __floats2half2_rn(g_c.w[hh][2 * j],  g_c.w[hh][2 * j + 1]);
        }
        if (td < NH * NB) {
            int hh = td / NB, q = td % NB;
            float g = g_c.gam[hh][q];
            sGam[hh][q] = __floats2half2_rn(g, g);
        }
        if (td < NH) {
            sTa[td] = __floats2half2_rn(g_c.ta[td], g_c.ta[td]);
            sU[td]  = __floats2half2_rn(g_c.u[td],  g_c.u[td]);
        }
        if (td == 0) sBo = g_c.bo;
    }
    __syncthreads();

    int t = blockIdx.x * blockDim.x + threadIdx.x;
    if (t >= N2) return;
    int n = t >> 1;
    int h = t & 1;

    __half2 x2[6];
    {
        const float4* xp = (const float4*)(x + (size_t)n * NB);
        float4 a0 = xp[0], a1 = xp[1], a2 = xp[2];
        x2[0] = __floats2half2_rn(a0.x, a0.y);
        x2[1] = __floats2half2_rn(a0.z, a0.w);
        x2[2] = __floats2half2_rn(a1.x, a1.y);
        x2[3] = __floats2half2_rn(a1.z, a1.w);
        x2[4] = __floats2half2_rn(a2.x, a2.y);
        x2[5] = __floats2half2_rn(a2.z, a2.w);
    }

    __half2 ah2 = sTa[h], uh2 = sU[h];
    __half2 t2[6], m2[6];
    #pragma unroll
    for (int j = 0; j < 6; j++) {
        t2[j] = __hfma2(x2[j], ah2, sTb[h][j]);
        m2[j] = __hfma2(x2[j], uh2, sW[h][j]);
    }

    float contrib[NB];
    #pragma unroll
    for (int q = 0; q < NB; q++) {
        __half2 gq2 = sGam[h][q];
        __half2 xq = ((q & 1) == 0) ? __low2half2(x2[q >> 1])
                                    : __high2half2(x2[q >> 1]);
        __half2 z = __floats2half2_rn(0.f, 0.f);
        __half2 rsA = z, rsB = z, dsA = z, dsB = z;
        #pragma unroll
        for (int j = 0; j < 3; j++) {
            __half2 sA = __hfma2(xq, t2[j],     __hfma2(x2[j],     gq2, sDel[h][q][j]));
            __half2 sB = __hfma2(xq, t2[j + 3], __hfma2(x2[j + 3], gq2, sDel[h][q][j + 3]));
            __half2 eA = h2ex2(sA);
            __half2 eB = h2ex2(sB);
            rsA = __hadd2(rsA, eA);
            rsB = __hadd2(rsB, eB);
            dsA = __hfma2(eA, m2[j], dsA);
            dsB = __hfma2(eB, m2[j + 3], dsB);
        }
        __half2 rs2 = __hadd2(rsA, rsB);
        __half2 ds2 = __hadd2(dsA, dsB);
        float2 rf = __half22float2(rs2);
        float2 df = __half22float2(ds2);
        contrib[q] = __fdividef(df.x + df.y, rf.x + rf.y);
    }

    #pragma unroll
    for (int q = 0; q < NB; q++)
        contrib[q] += __shfl_xor_sync(0xffffffffu, contrib[q], 1);

    if (h == 0) {
        float b = sBo;
        const float4* xp = (const float4*)(x + (size_t)n * NB);
        float4 a0 = xp[0], a1 = xp[1], a2 = xp[2];
        float4 o0 = make_float4(a0.x + contrib[0] + b,  a0.y + contrib[1] + b,
                                a0.z + contrib[2] + b,  a0.w + contrib[3] + b);
        float4 o1 = make_float4(a1.x + contrib[4] + b,  a1.y + contrib[5] + b,
                                a1.z + contrib[6] + b,  a1.w + contrib[7] + b);
        float4 o2 = make_float4(a2.x + contrib[8] + b,  a2.y + contrib[9] + b,
                                a2.z + contrib[10] + b, a2.w + contrib[11] + b);
        float4* op = (float4*)(out + (size_t)n * NB);
        op[0] = o0; op[1] = o1; op[2] = o2;
    }
}

// ---------------------------------------------------------------------------
extern "C" void kernel_launch(void* const* d_in, const int* in_sizes, int n_in,
                              void* d_out, int out_size) {
    const float* x  = (const float*)d_in[0];
    const float* we = (const float*)d_in[1];
    const float* be = (const float*)d_in[2];
    const float* bp = (const float*)d_in[3];
    const float* Wq = (const float*)d_in[4];
    const float* bq = (const float*)d_in[5];
    const float* Wk = (const float*)d_in[6];
    const float* bk = (const float*)d_in[7];
    const float* Wv = (const float*)d_in[8];
    const float* bv = (const float*)d_in[9];
    const float* Wo = (const float*)d_in[10];
    const float* bo = (const float*)d_in[11];
    float* out = (float*)d_out;

    int N = in_sizes[0] / NB;   // 65536 tokens
    int N2 = 2 * N;

    spec_setup<<<NH, 256>>>(we, be, bp, Wq, bq, Wk, bk, Wv, bv, Wo, bo);
    spec_main<<<(N2 + 255) / 256, 256>>>(x, out, N2);
}

// round 17
// speedup vs baseline: 1.2131x; 1.2131x over previous
#include <cuda_runtime.h>
#include <cuda_fp16.h>
#include <cstdint>

#define NB 12
#define DM 128
#define NH 2
#define HD 64
#define NSLICE 4
#define SETUP_BLOCKS (NH * NSLICE)   // 8

struct Consts {              // 368 floats = 92 float4
    float ta[NH];
    float u[NH];
    float bo;
    float pad[3];
    float tb[NH][NB];
    float gam[NH][NB];
    float w[NH][NB];
    float del[NH][NB][NB];
};
#define CONSTS_F4 (sizeof(Consts) / 16)   // 92

struct __align__(16) Tab {   // 992 B = 62 float4, laid out as main's smem
    __half2 del[NH][NB][8];
    __half2 tb[NH][6];
    __half2 w[NH][6];
    __half2 gam[NH][NB];
    __half2 ta[NH];
    __half2 u[NH];
    float bo;
    float pad[3];
};
#define TAB_F4 (sizeof(Tab) / 16)         // 62

__device__ __align__(16) Consts g_cp[NSLICE];
__device__ __align__(16) Tab g_tab;
__device__ int g_cnt;

__device__ __forceinline__ __half2 h2ex2(__half2 v) {
    uint32_t a = *reinterpret_cast<uint32_t*>(&v), b;
    asm("ex2.approx.f16x2 %0, %1;" : "=r"(b) : "r"(a));
    return *reinterpret_cast<__half2*>(&b);
}
__device__ __forceinline__ int ld_acq(const int* p) {
    int v;
    asm volatile("ld.acquire.gpu.b32 %0, [%1];" : "=r"(v) : "l"(p) : "memory");
    return v;
}

// ---------------------------------------------------------------------------
// Setup: ONE node, 8 blocks = (head h, 16-comp slice g) [R14 proven body].
// The LAST block to arrive additionally sums the partials and emits g_tab.
// ---------------------------------------------------------------------------
__global__ void __launch_bounds__(256) spec_setup(
        const float* __restrict__ we, const float* __restrict__ be,
        const float* __restrict__ bp,
        const float* __restrict__ Wq, const float* __restrict__ bq,
        const float* __restrict__ Wk, const float* __restrict__ bk,
        const float* __restrict__ Wv, const float* __restrict__ bv,
        const float* __restrict__ Wo, const float* __restrict__ bo) {
    __shared__ float4 sW4[32 * 33];
    __shared__ float4 sE4[13][32];
    __shared__ float  sC[32][13];
    __shared__ float4 sVPw[8][32];
    __shared__ float  sVP[DM];
    __shared__ int sLast;
    __shared__ __align__(16) float sRaw[CONSTS_F4 * 4];

    const int tid = threadIdx.x;
    const int h = blockIdx.x >> 2;
    const int g = blockIdx.x & 3;
    const int ibase = h * HD + g * 16;

    for (int idx = tid; idx < 13 * 32; idx += 256) {
        int e = idx >> 5, c = idx & 31;
        float4 v;
        if (e == 0) {
            v = ((const float4*)we)[c];
        } else {
            float4 b4 = ((const float4*)be)[c];
            float4 p4 = ((const float4*)bp)[(e - 1) * 32 + c];
            v = make_float4(b4.x + p4.x, b4.y + p4.y, b4.z + p4.z, b4.w + p4.w);
        }
        sE4[e][c] = v;
    }
    for (int idx = tid; idx < 32 * 32; idx += 256) {
        int r = idx >> 5, c = idx & 31;
        const float* W = (r < 16) ? Wq : Wk;
        int i = ibase + (r & 15);
        sW4[r * 33 + c] = ((const float4*)(W + i * DM))[c];
    }
    {
        int wid = tid >> 5, lane = tid & 31;
        float4 p = make_float4(0.f, 0.f, 0.f, 0.f);
        #pragma unroll
        for (int k = 0; k < 2; k++) {
            int i = ibase + wid * 2 + k;
            float wo = Wo[i];
            float4 v4 = ((const float4*)(Wv + i * DM))[lane];
            p.x = fmaf(wo, v4.x, p.x);
            p.y = fmaf(wo, v4.y, p.y);
            p.z = fmaf(wo, v4.z, p.z);
            p.w = fmaf(wo, v4.w, p.w);
        }
        sVPw[wid][lane] = p;
    }
    __syncthreads();

    if (tid < 32) {
        float4 s = make_float4(0.f, 0.f, 0.f, 0.f);
        #pragma unroll
        for (int w = 0; w < 8; w++) {
            float4 p = sVPw[w][tid];
            s.x += p.x; s.y += p.y; s.z += p.z; s.w += p.w;
        }
        ((float4*)sVP)[tid] = s;
    }

    for (int idx = tid; idx < 32 * 13; idx += 256) {
        int r = idx & 31;
        int e = idx >> 5;
        float a0 = 0.f, a1 = 0.f, a2 = 0.f, a3 = 0.f;
        #pragma unroll
        for (int c = 0; c < 32; c += 4) {
            float4 w0 = sW4[r * 33 + c],     e0 = sE4[e][c];
            float4 w1 = sW4[r * 33 + c + 1], e1 = sE4[e][c + 1];
            float4 w2 = sW4[r * 33 + c + 2], e2 = sE4[e][c + 2];
            float4 w3 = sW4[r * 33 + c + 3], e3 = sE4[e][c + 3];
            a0 = fmaf(w0.x, e0.x, fmaf(w0.y, e0.y, fmaf(w0.z, e0.z, fmaf(w0.w, e0.w, a0))));
            a1 = fmaf(w1.x, e1.x, fmaf(w1.y, e1.y, fmaf(w1.z, e1.z, fmaf(w1.w, e1.w, a1))));
            a2 = fmaf(w2.x, e2.x, fmaf(w2.y, e2.y, fmaf(w2.z, e2.z, fmaf(w2.w, e2.w, a2))));
            a3 = fmaf(w3.x, e3.x, fmaf(w3.y, e3.y, fmaf(w3.z, e3.z, fmaf(w3.w, e3.w, a3))));
        }
        float acc = (a0 + a1) + (a2 + a3);
        if (e > 0) acc += (r < 16) ? bq[ibase + r] : bk[ibase + r - 16];
        sC[r][e] = acc;
    }
    __syncthreads();

    const float cfac = 0.125f * 1.4426950408889634f;

    if (tid < 182) {
        int rr = tid;
        if (rr == 1 || (rr >= 26 && rr < 38)) {
            int e = (rr == 1) ? 0 : (rr - 26 + 1);
            const float4* A = (const float4*)sVP;
            float a0 = 0.f, a1 = 0.f, a2 = 0.f, a3 = 0.f;
            #pragma unroll
            for (int c = 0; c < 32; c += 4) {
                float4 v0 = A[c],     e0 = sE4[e][c];
                float4 v1 = A[c + 1], e1 = sE4[e][c + 1];
                float4 v2 = A[c + 2], e2 = sE4[e][c + 2];
                float4 v3 = A[c + 3], e3 = sE4[e][c + 3];
                a0 = fmaf(v0.x, e0.x, fmaf(v0.y, e0.y, fmaf(v0.z, e0.z, fmaf(v0.w, e0.w, a0))));
                a1 = fmaf(v1.x, e1.x, fmaf(v1.y, e1.y, fmaf(v1.z, e1.z, fmaf(v1.w, e1.w, a1))));
                a2 = fmaf(v2.x, e2.x, fmaf(v2.y, e2.y, fmaf(v2.z, e2.z, fmaf(v2.w, e2.w, a2))));
                a3 = fmaf(v3.x, e3.x, fmaf(v3.y, e3.y, fmaf(v3.z, e3.z, fmaf(v3.w, e3.w, a3))));
            }
            float acc = (a0 + a1) + (a2 + a3);
            if (rr == 1) {
                g_cp[g].u[h] = acc;
            } else {
                float bw = 0.f;
                #pragma unroll
                for (int il = 0; il < 16; il++)
                    bw = fmaf(bv[ibase + il], Wo[ibase + il], bw);
                g_cp[g].w[h][rr - 26] = acc + bw;
            }
        } else {
            const float* A;
            const float* B;
            float* dst;
            if (rr == 0)      { A = &sC[0][0];  B = &sC[16][0]; dst = &g_cp[g].ta[h]; }
            else if (rr < 14) { int b = rr - 2;
                                A = &sC[0][0];  B = &sC[16][1 + b]; dst = &g_cp[g].tb[h][b]; }
            else if (rr < 26) { int b = rr - 14;
                                A = &sC[0][1 + b]; B = &sC[16][0]; dst = &g_cp[g].gam[h][b]; }
            else              { int idx = rr - 38, q = idx / NB, k = idx % NB;
                                A = &sC[0][1 + q]; B = &sC[16][1 + k]; dst = &g_cp[g].del[h][q][k]; }
            float a0 = 0.f, a1 = 0.f;
            #pragma unroll
            for (int il = 0; il < 16; il += 2) {
                a0 = fmaf(A[il * 13],       B[il * 13],       a0);
                a1 = fmaf(A[(il + 1) * 13], B[(il + 1) * 13], a1);
            }
            *dst = (a0 + a1) * cfac;
        }
    }
    if (h == 0 && tid == 182) g_cp[g].bo = (g == 0) ? bo[0] : 0.f;
    if (h == 0 && tid >= 183 && tid < 186)
        ((float*)&g_cp[g])[5 + (tid - 183)] = 0.f;   // zero pad[0..2]

    // ---- last arriving block: sum partials -> half2 Tab ----
    __threadfence();
    __syncthreads();
    if (tid == 0) {
        int c = atomicAdd(&g_cnt, 1);
        sLast = (c == SETUP_BLOCKS - 1);
    }
    __syncthreads();
    if (!sLast) return;

    if (tid < CONSTS_F4) {
        const float4* p0 = (const float4*)&g_cp[0];
        const float4* p1 = (const float4*)&g_cp[1];
        const float4* p2 = (const float4*)&g_cp[2];
        const float4* p3 = (const float4*)&g_cp[3];
        float4 a = p0[tid], b = p1[tid], c = p2[tid], d = p3[tid];
        ((float4*)sRaw)[tid] = make_float4((a.x + b.x) + (c.x + d.x),
                                           (a.y + b.y) + (c.y + d.y),
                                           (a.z + b.z) + (c.z + d.z),
                                           (a.w + b.w) + (c.w + d.w));
    }
    __syncthreads();

    const Consts* C = (const Consts*)sRaw;
    for (int i = tid; i < NH * NB * 6; i += 256) {
        int hh = i / (NB * 6);
        int r = i % (NB * 6);
        int q = r / 6, j = r % 6;
        g_tab.del[hh][q][j] = __floats2half2_rn(C->del[hh][q][2 * j],
                                                C->del[hh][q][2 * j + 1]);
    }
    if (tid < NH * 6) {
        int hh = tid / 6, j = tid % 6;
        g_tab.tb[hh][j] = __floats2half2_rn(C->tb[hh][2 * j], C->tb[hh][2 * j + 1]);
        g_tab.w[hh][j]  = __floats2half2_rn(C->w[hh][2 * j],  C->w[hh][2 * j + 1]);
    }
    if (tid < NH * NB) {
        int hh = tid / NB, q = tid % NB;
        float gm = C->gam[hh][q];
        g_tab.gam[hh][q] = __floats2half2_rn(gm, gm);
    }
    if (tid < NH) {
        g_tab.ta[tid] = __floats2half2_rn(C->ta[tid], C->ta[tid]);
        g_tab.u[tid]  = __floats2half2_rn(C->u[tid],  C->u[tid]);
    }
    if (tid == 0) {
        g_tab.bo = C->bo;
        g_cnt = 0;                       // reset for next graph replay
    }
}

// ---------------------------------------------------------------------------
// Main kernel: trivial Tab prologue (62 coalesced float4) + PROVEN core.
// ---------------------------------------------------------------------------
__global__ void __launch_bounds__(256, 4) spec_main(const float* __restrict__ x,
                                                    float* __restrict__ out, int N2) {
    __shared__ Tab sT;
    {
        int td = threadIdx.x;
        if (td < TAB_F4)
            ((float4*)&sT)[td] = ((const float4*)&g_tab)[td];
    }
    __syncthreads();

    int t = blockIdx.x * blockDim.x + threadIdx.x;
    if (t >= N2) return;
    int n = t >> 1;
    int h = t & 1;

    __half2 x2[6];
    {
        const float4* xp = (const float4*)(x + (size_t)n * NB);
        float4 a0 = xp[0], a1 = xp[1], a2 = xp[2];
        x2[0] = __floats2half2_rn(a0.x, a0.y);
        x2[1] = __floats2half2_rn(a0.z, a0.w);
        x2[2] = __floats2half2_rn(a1.x, a1.y);
        x2[3] = __floats2half2_rn(a1.z, a1.w);
        x2[4] = __floats2half2_rn(a2.x, a2.y);
        x2[5] = __floats2half2_rn(a2.z, a2.w);
    }

    __half2 ah2 = sT.ta[h], uh2 = sT.u[h];
    __half2 t2[6], m2[6];
    #pragma unroll
    for (int j = 0; j < 6; j++) {
        t2[j] = __hfma2(x2[j], ah2, sT.tb[h][j]);
        m2[j] = __hfma2(x2[j], uh2, sT.w[h][j]);
    }

    float contrib[NB];
    #pragma unroll
    for (int q = 0; q < NB; q++) {
        __half2 gq2 = sT.gam[h][q];
        __half2 xq = ((q & 1) == 0) ? __low2half2(x2[q >> 1])
                                    : __high2half2(x2[q >> 1]);
        __half2 z = __floats2half2_rn(0.f, 0.f);
        __half2 rsA = z, rsB = z, dsA = z, dsB = z;
        #pragma unroll
        for (int j = 0; j < 3; j++) {
            __half2 sA = __hfma2(xq, t2[j],     __hfma2(x2[j],     gq2, sT.del[h][q][j]));
            __half2 sB = __hfma2(xq, t2[j + 3], __hfma2(x2[j + 3], gq2, sT.del[h][q][j + 3]));
            __half2 eA = h2ex2(sA);
            __half2 eB = h2ex2(sB);
            rsA = __hadd2(rsA, eA);
            rsB = __hadd2(rsB, eB);
            dsA = __hfma2(eA, m2[j], dsA);
            dsB = __hfma2(eB, m2[j + 3], dsB);
        }
        __half2 rs2 = __hadd2(rsA, rsB);
        __half2 ds2 = __hadd2(dsA, dsB);
        float2 rf = __half22float2(rs2);
        float2 df = __half22float2(ds2);
        contrib[q] = __fdividef(df.x + df.y, rf.x + rf.y);
    }

    #pragma unroll
    for (int q = 0; q < NB; q++)
        contrib[q] += __shfl_xor_sync(0xffffffffu, contrib[q], 1);

    if (h == 0) {
        float b = sT.bo;
        const float4* xp = (const float4*)(x + (size_t)n * NB);
        float4 a0 = xp[0], a1 = xp[1], a2 = xp[2];
        float4 o0 = make_float4(a0.x + contrib[0] + b,  a0.y + contrib[1] + b,
                                a0.z + contrib[2] + b,  a0.w + contrib[3] + b);
        float4 o1 = make_float4(a1.x + contrib[4] + b,  a1.y + contrib[5] + b,
                                a1.z + contrib[6] + b,  a1.w + contrib[7] + b);
        float4 o2 = make_float4(a2.x + contrib[8] + b,  a2.y + contrib[9] + b,
                                a2.z + contrib[10] + b, a2.w + contrib[11] + b);
        float4* op = (float4*)(out + (size_t)n * NB);
        op[0] = o0; op[1] = o1; op[2] = o2;
    }
}

// ---------------------------------------------------------------------------
extern "C" void kernel_launch(void* const* d_in, const int* in_sizes, int n_in,
                              void* d_out, int out_size) {
    const float* x  = (const float*)d_in[0];
    const float* we = (const float*)d_in[1];
    const float* be = (const float*)d_in[2];
    const float* bp = (const float*)d_in[3];
    const float* Wq = (const float*)d_in[4];
    const float* bq = (const float*)d_in[5];
    const float* Wk = (const float*)d_in[6];
    const float* bk = (const float*)d_in[7];
    const float* Wv = (const float*)d_in[8];
    const float* bv = (const float*)d_in[9];
    const float* Wo = (const float*)d_in[10];
    const float* bo = (const float*)d_in[11];
    float* out = (float*)d_out;

    int N = in_sizes[0] / NB;   // 65536 tokens
    int N2 = 2 * N;

    spec_setup<<<SETUP_BLOCKS, 256>>>(we, be, bp, Wq, bq, Wk, bk, Wv, bv, Wo, bo);
    spec_main<<<(N2 + 255) / 256, 256>>>(x, out, N2);
}